// round 8
// baseline (speedup 1.0000x reference)
#include <cuda_runtime.h>
#include <math.h>

#define D_   64
#define T_   128
#define B_   64
#define R_   20
#define SEE_ 10
#define H_   4
#define C_   4
#define NT   512

struct Smem {
  float h[D_];
  float v[2*D_];
  float vr[4*D_];
  float all_hv[SEE_*3*D_];
  float bg_r[SEE_];
  float q[H_*D_];
  float kk[H_*SEE_*D_];
  float logit[H_*SEE_];
  float att[H_*SEE_];
  float ws[SEE_];
  float bg_atts[6*D_];
  float his_atts[2*D_];
  float sc[T_+1];
  float pr[T_+1];
  float pn[T_+1];
  float peer[6*D_];
  float gru_in[4*D_];
  float gx[3*D_];
  float gh[3*D_];
  float red[8];
  float dw0, dw1;
  float hbuf[(T_+1)*D_];
  float vbuf[(T_+1)*2*D_];
  float rbuf[T_+1];
};

__device__ __forceinline__ float sigmoidf_(float x){ return 1.0f/(1.0f+expf(-x)); }

__global__ void __launch_bounds__(NT,1) cokt_kernel(
  const int* __restrict__ prob_id, const int* __restrict__ skills,
  const int* __restrict__ response, const int* __restrict__ bg_index,
  const int* __restrict__ mem_prob_ids, const int* __restrict__ mem_resp,
  const int* __restrict__ mem_concepts,
  const float* __restrict__ states_mem, const float* __restrict__ concept_emb,
  const float* __restrict__ prob_emb,
  const float* __restrict__ W_pred, const float* __restrict__ b_pred,
  const float* __restrict__ W_ih, const float* __restrict__ W_hh,
  const float* __restrict__ b_ih, const float* __restrict__ b_hh,
  const float* __restrict__ W_batch, const float* __restrict__ b_batch,
  const float* __restrict__ W_bg, const float* __restrict__ b_bg,
  const float* __restrict__ W_bgint, const float* __restrict__ b_bgint,
  const float* __restrict__ W_hisint, const float* __restrict__ b_hisint,
  const float* __restrict__ W_inmap, const float* __restrict__ b_inmap,
  const float* __restrict__ dir_w, const float* __restrict__ heads_map,
  float* __restrict__ out)
{
  extern __shared__ unsigned char smraw[];
  Smem* sm = reinterpret_cast<Smem*>(smraw);
  const int b    = blockIdx.x;
  const int tid  = threadIdx.x;
  const int lane = tid & 31;
  const int wid  = tid >> 5;

  // ---- init carry & buffer row 0 ----
  if (tid < D_){ sm->h[tid] = 0.f; sm->hbuf[tid] = 0.f; }
  if (tid >= D_ && tid < 3*D_) sm->vbuf[tid - D_] = 0.f;
  if (tid == NT-1){
    sm->rbuf[0] = 0.f;
    float w0 = dir_w[0], w1 = dir_w[1];
    float m  = fmaxf(w0, w1);
    float e0 = expf(w0 - m), e1 = expf(w1 - m);
    sm->dw0 = e0/(e0+e1); sm->dw1 = e1/(e0+e1);
  }
  __syncthreads();

  const float inv_s192 = 1.0f/sqrtf(192.0f);
  const float inv_s128 = 1.0f/sqrtf(128.0f);

  for (int t = 0; t < T_; ++t){
    const int   pid   = prob_id[t*B_ + b];
    const float respf = (float)response[t*B_ + b];

    // ================= S1: v (prob_rep of current item) + bg gather =================
    if (tid < 2*D_){
      int d = tid & (D_-1);
      if (tid < D_){
        float s = 0.f; int cnt = 0;
        #pragma unroll
        for (int c = 0; c < C_; ++c){
          int k = skills[(t*B_ + b)*C_ + c];
          if (k > 0){ s += concept_emb[(size_t)(k-1)*D_ + d]; cnt++; }
        }
        sm->v[d] = s / (cnt ? (float)cnt : 1.f);
      } else {
        sm->v[D_ + d] = (pid > 0) ? prob_emb[(size_t)(pid-1)*D_ + d] : 0.f;
      }
    }
    for (int i = tid; i < SEE_*3*D_; i += NT){
      int s = i / (3*D_);
      int k = i - s*3*D_;
      int idx = bg_index[(t*B_ + b)*R_ + s];
      float val;
      if (k < D_){
        val = states_mem[(size_t)idx*D_ + k];
      } else if (k < 2*D_){
        int d = k - D_;
        float ss = 0.f; int cnt = 0;
        #pragma unroll
        for (int c = 0; c < C_; ++c){
          int kc = mem_concepts[(size_t)idx*C_ + c];
          if (kc > 0){ ss += concept_emb[(size_t)(kc-1)*D_ + d]; cnt++; }
        }
        val = ss / (cnt ? (float)cnt : 1.f);
      } else {
        int d  = k - 2*D_;
        int mp = mem_prob_ids[idx];
        val = (mp > 0) ? prob_emb[(size_t)(mp-1)*D_ + d] : 0.f;
      }
      sm->all_hv[i] = val;
    }
    if (tid >= NT - SEE_){
      int s   = tid - (NT - SEE_);
      int idx = bg_index[(t*B_ + b)*R_ + s];
      sm->bg_r[s] = (float)mem_resp[idx];
    }
    __syncthreads();

    // ================= S2: kk (threads 0..255, W_bg read ONCE) | q (threads 256..511) =================
    if (tid < H_*D_){
      int hh = tid >> 6, d = tid & 63;
      float acc[SEE_];
      float bb = b_bg[hh*D_ + d];
      #pragma unroll
      for (int s = 0; s < SEE_; ++s) acc[s] = bb;
      const float* Wg = W_bg + (size_t)hh*3*D_*D_ + d;
      for (int k = 0; k < 3*D_; k += 2){
        float w0 = Wg[(size_t)k*D_];
        float w1 = Wg[(size_t)(k+1)*D_];
        #pragma unroll
        for (int s = 0; s < SEE_; ++s){
          float2 hv = *reinterpret_cast<const float2*>(&sm->all_hv[s*3*D_ + k]);
          acc[s] += hv.x*w0 + hv.y*w1;
        }
      }
      #pragma unroll
      for (int s = 0; s < SEE_; ++s) sm->kk[(hh*SEE_ + s)*D_ + d] = acc[s];
    } else {
      int u  = tid - H_*D_;
      int hh = u >> 6, d = u & 63;
      float acc = b_batch[hh*D_ + d];
      const float* Wb = W_batch + (size_t)hh*3*D_*D_ + d;
      #pragma unroll 4
      for (int k = 0; k < D_;   ++k) acc += sm->h[k] * Wb[(size_t)k*D_];
      #pragma unroll 4
      for (int k = 0; k < 2*D_; ++k) acc += sm->v[k] * Wb[(size_t)(D_+k)*D_];
      sm->q[u] = acc;
    }
    __syncthreads();

    // ================= S3: attention logits (warp per (h,s) pair) =================
    for (int p = wid; p < H_*SEE_; p += NT/32){
      int hh = p / SEE_;
      float a = sm->kk[p*D_ + lane]      * sm->q[hh*D_ + lane]
              + sm->kk[p*D_ + 32 + lane] * sm->q[hh*D_ + 32 + lane];
      #pragma unroll
      for (int o = 16; o; o >>= 1) a += __shfl_xor_sync(0xffffffffu, a, o);
      if (lane == 0) sm->logit[p] = a * inv_s192;
    }
    __syncthreads();

    // ================= S4: att softmax (threads 0..3) | history scores sc (warps 1..15) =================
    if (tid < H_){
      float mx = -1e30f;
      #pragma unroll
      for (int s = 0; s < SEE_; ++s) mx = fmaxf(mx, sm->logit[tid*SEE_ + s]);
      float sum = 0.f;
      #pragma unroll
      for (int s = 0; s < SEE_; ++s){
        float e = expf(sm->logit[tid*SEE_ + s] - mx);
        sm->att[tid*SEE_ + s] = e; sum += e;
      }
      float inv = 1.f/sum;
      #pragma unroll
      for (int s = 0; s < SEE_; ++s) sm->att[tid*SEE_ + s] *= inv;
    }
    if (wid >= 1){
      for (int j = wid-1; j <= t; j += (NT/32)-1){
        const float* vb = sm->vbuf + j*2*D_;
        float a = sm->v[lane]      * vb[lane]
                + sm->v[lane+32]   * vb[lane+32]
                + sm->v[lane+64]   * vb[lane+64]
                + sm->v[lane+96]   * vb[lane+96];
        #pragma unroll
        for (int o = 16; o; o >>= 1) a += __shfl_xor_sync(0xffffffffu, a, o);
        if (lane == 0) sm->sc[j] = a * inv_s128;
      }
    }
    __syncthreads();

    // ================= S5: history softmax (warp 0) | ws = hm·att (warp 1) =================
    if (wid == 0){
      float mx = -1e30f;
      for (int j = lane; j <= t; j += 32) mx = fmaxf(mx, sm->sc[j]);
      #pragma unroll
      for (int o = 16; o; o >>= 1) mx = fmaxf(mx, __shfl_xor_sync(0xffffffffu, mx, o));
      float sum = 0.f;
      for (int j = lane; j <= t; j += 32){
        float e = expf(sm->sc[j] - mx); sm->sc[j] = e; sum += e;
      }
      #pragma unroll
      for (int o = 16; o; o >>= 1) sum += __shfl_xor_sync(0xffffffffu, sum, o);
      float inv = 1.f/sum;
      for (int j = lane; j <= t; j += 32){
        float p  = sm->sc[j]*inv;
        float rb = sm->rbuf[j];
        sm->pr[j] = p*rb; sm->pn[j] = p*(1.f-rb);
      }
    } else if (wid == 1 && lane < SEE_){
      float a = 0.f;
      #pragma unroll
      for (int hh = 0; hh < H_; ++hh) a += heads_map[hh]*sm->att[hh*SEE_ + lane];
      sm->ws[lane] = a;
    }
    __syncthreads();

    // ================= S6: bg_atts (threads 0..383) | his_atts (threads 384..511) =================
    if (tid < 6*D_){
      bool lo  = tid < 3*D_;
      int kidx = lo ? tid : tid - 3*D_;
      float acc = 0.f;
      #pragma unroll
      for (int s = 0; s < SEE_; ++s){
        float r = sm->bg_r[s];
        float f = sm->all_hv[s*3*D_ + kidx] * (lo ? r : (1.f - r));
        acc += sm->ws[s]*f;
      }
      sm->bg_atts[tid] = acc;
    } else {
      int u = tid - 6*D_;       // 0..127
      int d = u & 63;
      const float* w = (u < D_) ? sm->pr : sm->pn;
      float acc = 0.f;
      for (int j = 0; j <= t; ++j) acc += w[j]*sm->hbuf[j*D_ + d];
      sm->his_atts[u] = acc;
    }
    __syncthreads();

    // ================= S7: peer (threads 0..383) | v_resp (threads 384..511) =================
    if (tid < 6*D_){
      float a1 = b_bgint[tid];
      #pragma unroll 4
      for (int k = 0; k < 6*D_; ++k) a1 += sm->bg_atts[k]*W_bgint[(size_t)k*6*D_ + tid];
      float a2 = b_hisint[tid];
      #pragma unroll 4
      for (int k = 0; k < 2*D_; ++k) a2 += sm->his_atts[k]*W_hisint[(size_t)k*6*D_ + tid];
      sm->peer[tid] = sm->dw0*a1 + sm->dw1*a2;
    } else {
      int u = tid - 6*D_;       // 0..127
      sm->vr[u]        = sm->v[u]*respf;
      sm->vr[2*D_ + u] = sm->v[u]*(1.f - respf);
    }
    __syncthreads();

    // ================= S8: gru_in (threads 0..255) | prob partials (threads 256..511) =================
    if (tid < 4*D_){
      float a = b_inmap[tid];
      #pragma unroll 4
      for (int k = 0; k < 6*D_; ++k) a += sm->peer[k]*W_inmap[(size_t)k*4*D_ + tid];
      #pragma unroll 4
      for (int k = 0; k < 4*D_; ++k) a += sm->vr[k]*W_inmap[(size_t)(6*D_+k)*4*D_ + tid];
      sm->gru_in[tid] = a;
    } else {
      int u = tid - 4*D_;       // 0..255
      float part = 0.f;
      for (int i = u; i < 9*D_; i += 4*D_){
        float xv = (i < 6*D_) ? sm->peer[i]
                 : ((i < 8*D_) ? sm->v[i - 6*D_] : sm->h[i - 8*D_]);
        part += xv*W_pred[i];
      }
      #pragma unroll
      for (int o = 16; o; o >>= 1) part += __shfl_xor_sync(0xffffffffu, part, o);
      if (lane == 0) sm->red[wid - 8] = part;
    }
    __syncthreads();

    // ================= S9: gx/gh (threads 0..191) | prob finalize (thread 192) =================
    if (tid < 3*D_){
      float a = b_ih[tid];
      #pragma unroll 4
      for (int k = 0; k < 4*D_; ++k) a += sm->gru_in[k]*W_ih[(size_t)k*3*D_ + tid];
      float g = b_hh[tid];
      #pragma unroll 4
      for (int k = 0; k < D_;   ++k) g += sm->h[k]*W_hh[(size_t)k*3*D_ + tid];
      sm->gx[tid] = a; sm->gh[tid] = g;
    } else if (tid == 3*D_){
      float s = b_pred[0];
      #pragma unroll
      for (int i = 0; i < 8; ++i) s += sm->red[i];
      out[b*T_ + t] = s;
    }
    __syncthreads();

    // ================= S10: GRU update + append to history buffers =================
    if (tid < D_){
      float r  = sigmoidf_(sm->gx[tid]          + sm->gh[tid]);
      float z  = sigmoidf_(sm->gx[D_   + tid]   + sm->gh[D_   + tid]);
      float n  = tanhf   (sm->gx[2*D_ + tid]    + r*sm->gh[2*D_ + tid]);
      float nh = (1.f - z)*n + z*sm->h[tid];
      sm->h[tid] = nh;
      sm->hbuf[(size_t)(t+1)*D_ + tid] = nh;
    } else if (tid < 3*D_){
      int u = tid - D_;
      sm->vbuf[(size_t)(t+1)*2*D_ + u] = sm->v[u];
    } else if (tid == 3*D_){
      sm->rbuf[t+1] = respf;
    }
    __syncthreads();
  }
}

extern "C" void kernel_launch(void* const* d_in, const int* in_sizes, int n_in,
                              void* d_out, int out_size)
{
  (void)in_sizes; (void)n_in; (void)out_size;
  cudaFuncSetAttribute(cokt_kernel, cudaFuncAttributeMaxDynamicSharedMemorySize,
                       (int)sizeof(Smem));
  cokt_kernel<<<B_, NT, sizeof(Smem)>>>(
    (const int*)  d_in[0],  // prob_id
    (const int*)  d_in[1],  // skills
    (const int*)  d_in[2],  // response
    (const int*)  d_in[3],  // bg_index
    (const int*)  d_in[4],  // mem_prob_ids
    (const int*)  d_in[5],  // mem_resp
    (const int*)  d_in[6],  // mem_concepts
    (const float*)d_in[7],  // states_mem
    (const float*)d_in[8],  // concept_emb
    (const float*)d_in[9],  // prob_emb
    (const float*)d_in[10], // W_pred
    (const float*)d_in[11], // b_pred
    (const float*)d_in[12], // W_ih
    (const float*)d_in[13], // W_hh
    (const float*)d_in[14], // b_ih
    (const float*)d_in[15], // b_hh
    (const float*)d_in[16], // W_batch
    (const float*)d_in[17], // b_batch
    (const float*)d_in[18], // W_bg
    (const float*)d_in[19], // b_bg
    (const float*)d_in[20], // W_bgint
    (const float*)d_in[21], // b_bgint
    (const float*)d_in[22], // W_hisint
    (const float*)d_in[23], // b_hisint
    (const float*)d_in[24], // W_inmap
    (const float*)d_in[25], // b_inmap
    (const float*)d_in[26], // dir_w
    (const float*)d_in[27], // heads_map
    (float*)d_out);
}

// round 9
// speedup vs baseline: 1.1152x; 1.1152x over previous
#include <cuda_runtime.h>
#include <math.h>

#define D_   64
#define T_   128
#define B_   64
#define R_   20
#define SEE_ 10
#define H_   4
#define C_   4
#define NT   512

// ---------------- transposed weight scratch (output-major rows) ----------------
__device__ __align__(16) float g_WbgT   [H_*D_*3*D_];   // [h][d][k]
__device__ __align__(16) float g_WbatchT[H_*D_*3*D_];   // [h][d][k]
__device__ __align__(16) float g_WbgintT[6*D_*6*D_];    // [j][k]
__device__ __align__(16) float g_WhisintT[6*D_*2*D_];   // [j][k]
__device__ __align__(16) float g_WinmapT[4*D_*10*D_];   // [j][k]
__device__ __align__(16) float g_WihT   [3*D_*4*D_];    // [j][k]
__device__ __align__(16) float g_WhhT   [3*D_*D_];      // [j][k]

__global__ void prep_kernel(const float* __restrict__ Wbg, const float* __restrict__ Wbatch,
                            const float* __restrict__ Wbgint, const float* __restrict__ Whisint,
                            const float* __restrict__ Winmap, const float* __restrict__ Wih,
                            const float* __restrict__ Whh)
{
  const int stride = gridDim.x*blockDim.x;
  const int i0 = blockIdx.x*blockDim.x + threadIdx.x;
  for (int o=i0; o<H_*D_*3*D_; o+=stride){
    int h=o/(D_*3*D_); int r=o-h*D_*3*D_; int d=r/(3*D_); int k=r-d*3*D_;
    int in=(h*3*D_+k)*D_+d;
    g_WbgT[o]=Wbg[in]; g_WbatchT[o]=Wbatch[in];
  }
  for (int o=i0;o<6*D_*6*D_;o+=stride){ int j=o/(6*D_); int k=o-j*6*D_; g_WbgintT[o]=Wbgint[k*6*D_+j]; }
  for (int o=i0;o<6*D_*2*D_;o+=stride){ int j=o/(2*D_); int k=o-j*2*D_; g_WhisintT[o]=Whisint[k*6*D_+j]; }
  for (int o=i0;o<4*D_*10*D_;o+=stride){ int j=o/(10*D_); int k=o-j*10*D_; g_WinmapT[o]=Winmap[k*4*D_+j]; }
  for (int o=i0;o<3*D_*4*D_;o+=stride){ int j=o/(4*D_); int k=o-j*4*D_; g_WihT[o]=Wih[k*3*D_+j]; }
  for (int o=i0;o<3*D_*D_; o+=stride){ int j=o/D_;    int k=o-j*D_;    g_WhhT[o]=Whh[k*3*D_+j]; }
}

// ---------------- packed f32x2 helpers ----------------
__device__ __forceinline__ void ffma2(unsigned long long& a, unsigned long long x, unsigned long long w){
  asm("fma.rn.f32x2 %0, %1, %2, %0;" : "+l"(a) : "l"(x), "l"(w));
}
__device__ __forceinline__ float upsum(unsigned long long a){
  float lo, hi;
  asm("mov.b64 {%0,%1}, %2;" : "=f"(lo), "=f"(hi) : "l"(a));
  return lo + hi;
}

struct __align__(16) Smem {
  // float4 / ulonglong2 accessed arrays (all sizes multiples of 4 floats)
  float h[D_];
  float v[2*D_];
  float x10[10*D_];          // [peer(384) | v*r(128) | v*(1-r)(128)]
  float all_hv[SEE_*3*D_];
  float q[H_*D_];
  float kk[H_*SEE_*D_];
  float bg_atts[6*D_];
  float his_atts[2*D_];
  float gru_in[4*D_];
  float gx[3*D_];
  float gh[3*D_];
  float hbuf[(T_+1)*D_];
  float vbuf[(T_+1)*2*D_];
  // scalar-accessed
  float bg_r[SEE_];
  float logit[H_*SEE_];
  float att[H_*SEE_];
  float ws[SEE_];
  float sc[T_+1];
  float pr[T_+1];
  float pn[T_+1];
  float rbuf[T_+1];
  float red[8];
  float dw0, dw1;
};

__device__ __forceinline__ float sigmoidf_(float x){ return 1.0f/(1.0f+expf(-x)); }

__global__ void __launch_bounds__(NT,1) cokt_kernel(
  const int* __restrict__ prob_id, const int* __restrict__ skills,
  const int* __restrict__ response, const int* __restrict__ bg_index,
  const int* __restrict__ mem_prob_ids, const int* __restrict__ mem_resp,
  const int* __restrict__ mem_concepts,
  const float* __restrict__ states_mem, const float* __restrict__ concept_emb,
  const float* __restrict__ prob_emb,
  const float* __restrict__ W_pred, const float* __restrict__ b_pred,
  const float* __restrict__ b_ih, const float* __restrict__ b_hh,
  const float* __restrict__ b_batch, const float* __restrict__ b_bg,
  const float* __restrict__ b_bgint, const float* __restrict__ b_hisint,
  const float* __restrict__ b_inmap,
  const float* __restrict__ dir_w, const float* __restrict__ heads_map,
  float* __restrict__ out)
{
  extern __shared__ unsigned char smraw[];
  Smem* sm = reinterpret_cast<Smem*>(smraw);
  const int b    = blockIdx.x;
  const int tid  = threadIdx.x;
  const int lane = tid & 31;
  const int wid  = tid >> 5;

  if (tid < D_){ sm->h[tid] = 0.f; sm->hbuf[tid] = 0.f; }
  if (tid >= D_ && tid < 3*D_) sm->vbuf[tid - D_] = 0.f;
  if (tid == NT-1){
    sm->rbuf[0] = 0.f;
    float w0 = dir_w[0], w1 = dir_w[1];
    float m  = fmaxf(w0, w1);
    float e0 = expf(w0 - m), e1 = expf(w1 - m);
    sm->dw0 = e0/(e0+e1); sm->dw1 = e1/(e0+e1);
  }
  __syncthreads();

  const float inv_s192 = 1.0f/sqrtf(192.0f);
  const float inv_s128 = 1.0f/sqrtf(128.0f);

  for (int t = 0; t < T_; ++t){
    const int   pid   = prob_id[t*B_ + b];
    const float respf = (float)response[t*B_ + b];

    // ============ S1: v + bg gather ============
    if (tid < 2*D_){
      int d = tid & (D_-1);
      if (tid < D_){
        float s = 0.f; int cnt = 0;
        #pragma unroll
        for (int c = 0; c < C_; ++c){
          int k = skills[(t*B_ + b)*C_ + c];
          if (k > 0){ s += concept_emb[(size_t)(k-1)*D_ + d]; cnt++; }
        }
        sm->v[d] = s / (cnt ? (float)cnt : 1.f);
      } else {
        sm->v[D_ + d] = (pid > 0) ? prob_emb[(size_t)(pid-1)*D_ + d] : 0.f;
      }
    }
    for (int i = tid; i < SEE_*3*D_; i += NT){
      int s = i / (3*D_);
      int k = i - s*3*D_;
      int idx = bg_index[(t*B_ + b)*R_ + s];
      float val;
      if (k < D_){
        val = states_mem[(size_t)idx*D_ + k];
      } else if (k < 2*D_){
        int d = k - D_;
        float ss = 0.f; int cnt = 0;
        #pragma unroll
        for (int c = 0; c < C_; ++c){
          int kc = mem_concepts[(size_t)idx*C_ + c];
          if (kc > 0){ ss += concept_emb[(size_t)(kc-1)*D_ + d]; cnt++; }
        }
        val = ss / (cnt ? (float)cnt : 1.f);
      } else {
        int d  = k - 2*D_;
        int mp = mem_prob_ids[idx];
        val = (mp > 0) ? prob_emb[(size_t)(mp-1)*D_ + d] : 0.f;
      }
      sm->all_hv[i] = val;
    }
    if (tid >= NT - SEE_){
      int s   = tid - (NT - SEE_);
      int idx = bg_index[(t*B_ + b)*R_ + s];
      sm->bg_r[s] = (float)mem_resp[idx];
    }
    __syncthreads();

    // ============ S2: kk (0..255) | q (256..511), transposed rows + f32x2 ============
    if (tid < H_*D_){
      int hh = tid >> 6, d = tid & 63;
      const ulonglong2* Wg = reinterpret_cast<const ulonglong2*>(
          g_WbgT + (size_t)(hh*D_ + d)*3*D_);
      unsigned long long acc[SEE_];
      #pragma unroll
      for (int s = 0; s < SEE_; ++s) acc[s] = 0ull;
      #pragma unroll 4
      for (int k4 = 0; k4 < 48; ++k4){
        ulonglong2 w = Wg[k4];
        #pragma unroll
        for (int s = 0; s < SEE_; ++s){
          ulonglong2 hv = reinterpret_cast<const ulonglong2*>(sm->all_hv + s*3*D_)[k4];
          ffma2(acc[s], hv.x, w.x);
          ffma2(acc[s], hv.y, w.y);
        }
      }
      float bb = b_bg[hh*D_ + d];
      #pragma unroll
      for (int s = 0; s < SEE_; ++s)
        sm->kk[(hh*SEE_ + s)*D_ + d] = bb + upsum(acc[s]);
    } else {
      int u  = tid - H_*D_;
      int hh = u >> 6, d = u & 63;
      const ulonglong2* Wb = reinterpret_cast<const ulonglong2*>(
          g_WbatchT + (size_t)(hh*D_ + d)*3*D_);
      unsigned long long a0 = 0ull, a1 = 0ull;
      const ulonglong2* hp = reinterpret_cast<const ulonglong2*>(sm->h);
      #pragma unroll
      for (int k = 0; k < 16; ++k){
        ulonglong2 w = Wb[k], x = hp[k];
        ffma2(a0, x.x, w.x); ffma2(a1, x.y, w.y);
      }
      const ulonglong2* vp = reinterpret_cast<const ulonglong2*>(sm->v);
      #pragma unroll
      for (int k = 0; k < 32; ++k){
        ulonglong2 w = Wb[16+k], x = vp[k];
        ffma2(a0, x.x, w.x); ffma2(a1, x.y, w.y);
      }
      sm->q[u] = b_batch[hh*D_ + d] + upsum(a0) + upsum(a1);
    }
    __syncthreads();

    // ============ S3: attention logits ============
    for (int p = wid; p < H_*SEE_; p += NT/32){
      int hh = p / SEE_;
      float a = sm->kk[p*D_ + lane]      * sm->q[hh*D_ + lane]
              + sm->kk[p*D_ + 32 + lane] * sm->q[hh*D_ + 32 + lane];
      #pragma unroll
      for (int o = 16; o; o >>= 1) a += __shfl_xor_sync(0xffffffffu, a, o);
      if (lane == 0) sm->logit[p] = a * inv_s192;
    }
    __syncthreads();

    // ============ S4: att softmax (0..3) | history scores (warps 1..15) ============
    if (tid < H_){
      float mx = -1e30f;
      #pragma unroll
      for (int s = 0; s < SEE_; ++s) mx = fmaxf(mx, sm->logit[tid*SEE_ + s]);
      float sum = 0.f;
      #pragma unroll
      for (int s = 0; s < SEE_; ++s){
        float e = expf(sm->logit[tid*SEE_ + s] - mx);
        sm->att[tid*SEE_ + s] = e; sum += e;
      }
      float inv = 1.f/sum;
      #pragma unroll
      for (int s = 0; s < SEE_; ++s) sm->att[tid*SEE_ + s] *= inv;
    }
    if (wid >= 1){
      float4 myv = reinterpret_cast<const float4*>(sm->v)[lane];
      for (int j = wid-1; j <= t; j += (NT/32)-1){
        float4 x = reinterpret_cast<const float4*>(sm->vbuf + j*2*D_)[lane];
        float a = myv.x*x.x + myv.y*x.y + myv.z*x.z + myv.w*x.w;
        #pragma unroll
        for (int o = 16; o; o >>= 1) a += __shfl_xor_sync(0xffffffffu, a, o);
        if (lane == 0) sm->sc[j] = a * inv_s128;
      }
    }
    __syncthreads();

    // ============ S5: history softmax (warp 0) | ws (warp 1) ============
    if (wid == 0){
      float mx = -1e30f;
      for (int j = lane; j <= t; j += 32) mx = fmaxf(mx, sm->sc[j]);
      #pragma unroll
      for (int o = 16; o; o >>= 1) mx = fmaxf(mx, __shfl_xor_sync(0xffffffffu, mx, o));
      float sum = 0.f;
      for (int j = lane; j <= t; j += 32){
        float e = expf(sm->sc[j] - mx); sm->sc[j] = e; sum += e;
      }
      #pragma unroll
      for (int o = 16; o; o >>= 1) sum += __shfl_xor_sync(0xffffffffu, sum, o);
      float inv = 1.f/sum;
      for (int j = lane; j <= t; j += 32){
        float p  = sm->sc[j]*inv;
        float rb = sm->rbuf[j];
        sm->pr[j] = p*rb; sm->pn[j] = p*(1.f-rb);
      }
    } else if (wid == 1 && lane < SEE_){
      float a = 0.f;
      #pragma unroll
      for (int hh = 0; hh < H_; ++hh) a += heads_map[hh]*sm->att[hh*SEE_ + lane];
      sm->ws[lane] = a;
    }
    __syncthreads();

    // ============ S6: bg_atts (0..383) | his_atts (384..511) ============
    if (tid < 6*D_){
      bool lo  = tid < 3*D_;
      int kidx = lo ? tid : tid - 3*D_;
      float acc = 0.f;
      #pragma unroll
      for (int s = 0; s < SEE_; ++s){
        float r = sm->bg_r[s];
        float f = sm->all_hv[s*3*D_ + kidx] * (lo ? r : (1.f - r));
        acc += sm->ws[s]*f;
      }
      sm->bg_atts[tid] = acc;
    } else {
      int u = tid - 6*D_;
      int d = u & 63;
      const float* w = (u < D_) ? sm->pr : sm->pn;
      float a0 = 0.f, a1 = 0.f;
      int j = 0;
      for (; j + 1 <= t; j += 2){
        a0 += w[j]  *sm->hbuf[j*D_ + d];
        a1 += w[j+1]*sm->hbuf[(j+1)*D_ + d];
      }
      if (j <= t) a0 += w[j]*sm->hbuf[j*D_ + d];
      sm->his_atts[u] = a0 + a1;
    }
    __syncthreads();

    // ============ S7: peer -> x10[0..383] (0..383) | v_resp -> x10[384..639] ============
    if (tid < 6*D_){
      const ulonglong2* Wb = reinterpret_cast<const ulonglong2*>(g_WbgintT  + (size_t)tid*6*D_);
      const ulonglong2* Wh = reinterpret_cast<const ulonglong2*>(g_WhisintT + (size_t)tid*2*D_);
      const ulonglong2* xb = reinterpret_cast<const ulonglong2*>(sm->bg_atts);
      const ulonglong2* xh = reinterpret_cast<const ulonglong2*>(sm->his_atts);
      unsigned long long a0 = 0ull, a1 = 0ull;
      #pragma unroll 8
      for (int k = 0; k < 96; ++k){
        ulonglong2 w = Wb[k], x = xb[k];
        ffma2(a0, x.x, w.x); ffma2(a1, x.y, w.y);
      }
      unsigned long long b0 = 0ull, b1 = 0ull;
      #pragma unroll
      for (int k = 0; k < 32; ++k){
        ulonglong2 w = Wh[k], x = xh[k];
        ffma2(b0, x.x, w.x); ffma2(b1, x.y, w.y);
      }
      float A = b_bgint[tid]  + upsum(a0) + upsum(a1);
      float Bv= b_hisint[tid] + upsum(b0) + upsum(b1);
      sm->x10[tid] = sm->dw0*A + sm->dw1*Bv;
    } else {
      int u = tid - 6*D_;  // 0..127
      float vv = sm->v[u];
      sm->x10[6*D_ + u]        = vv*respf;
      sm->x10[6*D_ + 2*D_ + u] = vv*(1.f - respf);
    }
    __syncthreads();

    // ============ S8: gru_in (0..255) | prob partials (256..511) ============
    if (tid < 4*D_){
      const ulonglong2* W = reinterpret_cast<const ulonglong2*>(g_WinmapT + (size_t)tid*10*D_);
      const ulonglong2* x = reinterpret_cast<const ulonglong2*>(sm->x10);
      unsigned long long a0 = 0ull, a1 = 0ull;
      #pragma unroll 8
      for (int k = 0; k < 160; ++k){
        ulonglong2 w = W[k], xx = x[k];
        ffma2(a0, xx.x, w.x); ffma2(a1, xx.y, w.y);
      }
      sm->gru_in[tid] = b_inmap[tid] + upsum(a0) + upsum(a1);
    } else {
      int u = tid - 4*D_;   // 0..255
      float part = 0.f;
      for (int i = u; i < 9*D_; i += 4*D_){
        float xv = (i < 6*D_) ? sm->x10[i]
                 : ((i < 8*D_) ? sm->v[i - 6*D_] : sm->h[i - 8*D_]);
        part += xv*W_pred[i];
      }
      #pragma unroll
      for (int o = 16; o; o >>= 1) part += __shfl_xor_sync(0xffffffffu, part, o);
      if (lane == 0) sm->red[wid - 8] = part;
    }
    __syncthreads();

    // ============ S9: gx/gh (0..191) | prob finalize (192) ============
    if (tid < 3*D_){
      const ulonglong2* Wi = reinterpret_cast<const ulonglong2*>(g_WihT + (size_t)tid*4*D_);
      const ulonglong2* xg = reinterpret_cast<const ulonglong2*>(sm->gru_in);
      unsigned long long a0 = 0ull, a1 = 0ull;
      #pragma unroll 8
      for (int k = 0; k < 64; ++k){
        ulonglong2 w = Wi[k], x = xg[k];
        ffma2(a0, x.x, w.x); ffma2(a1, x.y, w.y);
      }
      const ulonglong2* Wx = reinterpret_cast<const ulonglong2*>(g_WhhT + (size_t)tid*D_);
      const ulonglong2* hp = reinterpret_cast<const ulonglong2*>(sm->h);
      unsigned long long g0 = 0ull, g1 = 0ull;
      #pragma unroll
      for (int k = 0; k < 16; ++k){
        ulonglong2 w = Wx[k], x = hp[k];
        ffma2(g0, x.x, w.x); ffma2(g1, x.y, w.y);
      }
      sm->gx[tid] = b_ih[tid] + upsum(a0) + upsum(a1);
      sm->gh[tid] = b_hh[tid] + upsum(g0) + upsum(g1);
    } else if (tid == 3*D_){
      float s = b_pred[0];
      #pragma unroll
      for (int i = 0; i < 8; ++i) s += sm->red[i];
      out[b*T_ + t] = s;
    }
    __syncthreads();

    // ============ S10: GRU update + append history ============
    if (tid < D_){
      float r  = sigmoidf_(sm->gx[tid]        + sm->gh[tid]);
      float z  = sigmoidf_(sm->gx[D_   + tid] + sm->gh[D_   + tid]);
      float n  = tanhf   (sm->gx[2*D_ + tid]  + r*sm->gh[2*D_ + tid]);
      float nh = (1.f - z)*n + z*sm->h[tid];
      sm->h[tid] = nh;
      sm->hbuf[(size_t)(t+1)*D_ + tid] = nh;
    } else if (tid < 3*D_){
      int u = tid - D_;
      sm->vbuf[(size_t)(t+1)*2*D_ + u] = sm->v[u];
    } else if (tid == 3*D_){
      sm->rbuf[t+1] = respf;
    }
    __syncthreads();
  }
}

extern "C" void kernel_launch(void* const* d_in, const int* in_sizes, int n_in,
                              void* d_out, int out_size)
{
  (void)in_sizes; (void)n_in; (void)out_size;
  // transpose weights into __device__ scratch (deterministic, graph-capturable)
  prep_kernel<<<256, 256>>>(
    (const float*)d_in[18], // W_bg
    (const float*)d_in[16], // W_batch
    (const float*)d_in[20], // W_bgint
    (const float*)d_in[22], // W_hisint
    (const float*)d_in[24], // W_inmap
    (const float*)d_in[12], // W_ih
    (const float*)d_in[13]);// W_hh

  cudaFuncSetAttribute(cokt_kernel, cudaFuncAttributeMaxDynamicSharedMemorySize,
                       (int)sizeof(Smem));
  cokt_kernel<<<B_, NT, sizeof(Smem)>>>(
    (const int*)  d_in[0],  // prob_id
    (const int*)  d_in[1],  // skills
    (const int*)  d_in[2],  // response
    (const int*)  d_in[3],  // bg_index
    (const int*)  d_in[4],  // mem_prob_ids
    (const int*)  d_in[5],  // mem_resp
    (const int*)  d_in[6],  // mem_concepts
    (const float*)d_in[7],  // states_mem
    (const float*)d_in[8],  // concept_emb
    (const float*)d_in[9],  // prob_emb
    (const float*)d_in[10], // W_pred
    (const float*)d_in[11], // b_pred
    (const float*)d_in[14], // b_ih
    (const float*)d_in[15], // b_hh
    (const float*)d_in[17], // b_batch
    (const float*)d_in[19], // b_bg
    (const float*)d_in[21], // b_bgint
    (const float*)d_in[23], // b_hisint
    (const float*)d_in[25], // b_inmap
    (const float*)d_in[26], // dir_w
    (const float*)d_in[27], // heads_map
    (float*)d_out);
}